// round 4
// baseline (speedup 1.0000x reference)
#include <cuda_runtime.h>

#define Nn 8192
#define Cc 100
#define Dd 128
#define Hh 128
#define Oo 64
#define TPC 32                 // tokens per CTA chunk
#define NPAIR (TPC / 2)        // 16 token pairs
#define XSTRIDE 256            // words per pair-row (128 f32x2)
#define MAXW 356
#define NB 8
#define BT 1024

// ---------------- packed f32x2 helpers ----------------
#define FMA2(d, a, b) asm("fma.rn.f32x2 %0, %1, %2, %0;" : "+l"(d) : "l"(a), "l"(b))
#define DUP2(d, s)    asm("mov.b64 %0, {%1, %1};" : "=l"(d) : "f"(s))
#define PK2(d, lo, hi) asm("mov.b64 %0, {%1, %2};" : "=l"(d) : "f"(lo), "f"(hi))
#define UNPK2(lo, hi, s) asm("mov.b64 {%0, %1}, %2;" : "=f"(lo), "=f"(hi) : "l"(s))

// ---------------- scratch (no allocations allowed) ----------------
__device__ int g_bhist[NB * Cc];
__device__ int g_bbase[NB * Cc];
__device__ int g_perm[Nn];
__device__ int g_workCat[MAXW];
__device__ int g_workStart[MAXW];
__device__ int g_workCnt[MAXW];
__device__ int g_numWork;
__device__ int g_done;   // zero-init; reset by last block each run

// fused: per-block histogram (SMEM atomics) + last-block scan/worklist
__global__ void k_histscan(const int* __restrict__ cat) {
    __shared__ int h[Cc];
    __shared__ int isLast;
    int t = threadIdx.x, b = blockIdx.x;
    if (t < Cc) h[t] = 0;
    __syncthreads();
    atomicAdd(&h[cat[b * BT + t]], 1);
    __syncthreads();
    if (t < Cc) g_bhist[b * Cc + t] = h[t];
    __threadfence();
    if (t == 0) {
        int v = atomicAdd(&g_done, 1);
        isLast = (v == NB - 1);
    }
    __syncthreads();
    if (!isLast) return;
    __threadfence();

    // ---- scan (runs in the last-finishing block only) ----
    __shared__ int tot[Cc];
    __shared__ int off[Cc];
    __shared__ int coff[Cc];
    if (t < Cc) {
        int s = 0;
        #pragma unroll
        for (int bb = 0; bb < NB; bb++) s += g_bhist[bb * Cc + t];
        tot[t] = s;
    }
    __syncthreads();
    if (t == 0) {
        int r = 0, cr = 0;
        for (int c = 0; c < Cc; c++) {
            off[c] = r;  r += tot[c];
            coff[c] = cr; cr += (tot[c] + TPC - 1) / TPC;
        }
        g_numWork = cr;
        g_done = 0;                         // reset for next graph replay
    }
    __syncthreads();
    if (t < Cc) {
        int run = off[t];
        #pragma unroll
        for (int bb = 0; bb < NB; bb++) {
            g_bbase[bb * Cc + t] = run;
            run += g_bhist[bb * Cc + t];
        }
        int nch = (tot[t] + TPC - 1) / TPC;
        for (int j = 0; j < nch; j++) {
            int wi = coff[t] + j;
            g_workCat[wi]   = t;
            g_workStart[wi] = off[t] + j * TPC;
            int rem = tot[t] - j * TPC;
            g_workCnt[wi]   = rem < TPC ? rem : TPC;
        }
    }
}

// scatter: SMEM cursor atomics only
__global__ void k_scatter(const int* __restrict__ cat) {
    __shared__ int cur[Cc];
    int t = threadIdx.x, b = blockIdx.x;
    if (t < Cc) cur[t] = g_bbase[b * Cc + t];
    __syncthreads();
    int id = b * BT + t;
    int pos = atomicAdd(&cur[cat[id]], 1);
    g_perm[pos] = id;
}

// ---------------- main fused MLP: one CTA = (category, 32-token chunk) ----------------
// Warp w: pair group pg = w&3 (4 pairs = 8 tokens), column-half ch = w>>2.
// Layer 1: warp covers H cols [64*ch, 64*ch+64), lane owns 2 cols.
// Layer 2: warp covers O cols [32*ch, 32*ch+32), lane owns 1 col.
// Each W element is reused by 8 tokens -> W crossbar traffic halved vs round 3.
// SMEM = W1 (64KB) + W2 (32KB) + xp (16KB) = 112KB -> 2 CTAs/SM. h overwrites xp.
__global__ void __launch_bounds__(256, 2)
k_mlp(const float* __restrict__ x,
      const float* __restrict__ W1, const float* __restrict__ b1,
      const float* __restrict__ W2, const float* __restrict__ b2,
      float* __restrict__ out) {
    extern __shared__ float sm[];
    float* W1s = sm;                      // 16384 f (64KB)  [d][h]
    float* W2s = W1s + Dd * Hh;           // 8192 f  (32KB)  [k][o]
    float* xp  = W2s + Hh * Oo;           // 16*256 = 4096 f : pair-major packed x / h

    int w = blockIdx.x;
    if (w >= g_numWork) return;
    int c     = g_workCat[w];
    int start = g_workStart[w];
    int cnt   = g_workCnt[w];
    int t = threadIdx.x;

    // ---- stage weights (coalesced float4) ----
    const float4* W1g = (const float4*)(W1 + (size_t)c * Dd * Hh);
    float4* W1s4 = (float4*)W1s;
    #pragma unroll 4
    for (int i = t; i < Dd * Hh / 4; i += 256) W1s4[i] = W1g[i];
    const float4* W2g = (const float4*)(W2 + (size_t)c * Hh * Oo);
    float4* W2s4 = (float4*)W2s;
    #pragma unroll 2
    for (int i = t; i < Hh * Oo / 4; i += 256) W2s4[i] = W2g[i];

    // ---- stage x transposed+pair-packed: xp[p][d] = (x_{2p}[d], x_{2p+1}[d]) ----
    #pragma unroll
    for (int i = t; i < NPAIR * 32; i += 256) {
        int p = i >> 5, q = i & 31;            // q indexes d-quads
        int iA = 2 * p, iB = 2 * p + 1;
        int tA = (iA < cnt) ? g_perm[start + iA] : -1;
        int tB = (iB < cnt) ? g_perm[start + iB] : -1;
        float4 a = (tA >= 0) ? ((const float4*)(x + (size_t)tA * Dd))[q]
                             : make_float4(0.f, 0.f, 0.f, 0.f);
        float4 bb = (tB >= 0) ? ((const float4*)(x + (size_t)tB * Dd))[q]
                              : make_float4(0.f, 0.f, 0.f, 0.f);
        float* dst = xp + (size_t)p * XSTRIDE + 8 * q;
        ((float4*)dst)[0] = make_float4(a.x, bb.x, a.y, bb.y);
        ((float4*)dst)[1] = make_float4(a.z, bb.z, a.w, bb.w);
    }
    __syncthreads();

    int warp = t >> 5, lane = t & 31;
    int pg = warp & 3;                    // pair group: 4 pairs (8 tokens)
    int ch = warp >> 2;                   // column half
    int p0 = pg * 4;
    bool active = (pg * 8 < cnt);         // warp has at least one real token

    // ---- layer 1: 8 packed accumulators (4 pairs x 2 cols) ----
    int cb = 64 * ch;                     // H col base for this warp
    int c0 = cb + 2 * lane;               // lane's first col
    unsigned long long acc[4][2];
    #pragma unroll
    for (int pp = 0; pp < 4; pp++) { acc[pp][0] = 0ULL; acc[pp][1] = 0ULL; }

    if (active) {
        #pragma unroll 4
        for (int d = 0; d < Dd; d += 2) {
            float2 wa = *(const float2*)(W1s + (size_t)d * Hh + c0);
            float2 wb = *(const float2*)(W1s + (size_t)(d + 1) * Hh + c0);
            unsigned long long wa0, wa1, wb0, wb1;
            DUP2(wa0, wa.x); DUP2(wa1, wa.y);
            DUP2(wb0, wb.x); DUP2(wb1, wb.y);
            #pragma unroll
            for (int pp = 0; pp < 4; pp++) {
                ulonglong2 xv = *(const ulonglong2*)(xp + (size_t)(p0 + pp) * XSTRIDE + 2 * d);
                FMA2(acc[pp][0], xv.x, wa0); FMA2(acc[pp][1], xv.x, wa1);
                FMA2(acc[pp][0], xv.y, wb0); FMA2(acc[pp][1], xv.y, wb1);
            }
        }
    }

    __syncthreads();   // all warps done reading xp before h overwrites it

    if (active) {
        // epilogue 1: bias + relu, store pair-packed h in place over xp
        float2 bv = *(const float2*)(b1 + (size_t)c * Hh + c0);
        #pragma unroll
        for (int pp = 0; pp < 4; pp++) {
            float l0, h0, l1, h1;
            UNPK2(l0, h0, acc[pp][0]);
            UNPK2(l1, h1, acc[pp][1]);
            l0 = fmaxf(l0 + bv.x, 0.f); h0 = fmaxf(h0 + bv.x, 0.f);
            l1 = fmaxf(l1 + bv.y, 0.f); h1 = fmaxf(h1 + bv.y, 0.f);
            ulonglong2 v;
            PK2(v.x, l0, h0);
            PK2(v.y, l1, h1);
            *(ulonglong2*)(xp + (size_t)(p0 + pp) * XSTRIDE + 2 * c0) = v;
        }
    }

    __syncthreads();   // h complete before layer 2 reads

    if (!active) return;

    // ---- layer 2: 4 packed accumulators (4 pairs x 1 col) ----
    int col = 32 * ch + lane;             // lane's O col
    unsigned long long acc2[4];
    acc2[0] = acc2[1] = acc2[2] = acc2[3] = 0ULL;

    #pragma unroll 4
    for (int k = 0; k < Hh; k += 2) {
        float wA = W2s[(size_t)k * Oo + col];
        float wB = W2s[(size_t)(k + 1) * Oo + col];
        unsigned long long wA0, wB0;
        DUP2(wA0, wA); DUP2(wB0, wB);
        #pragma unroll
        for (int pp = 0; pp < 4; pp++) {
            ulonglong2 hv = *(const ulonglong2*)(xp + (size_t)(p0 + pp) * XSTRIDE + 2 * k);
            FMA2(acc2[pp], hv.x, wA0);
            FMA2(acc2[pp], hv.y, wB0);
        }
    }

    // epilogue 2: bias + store (unpack token pairs)
    {
        float bb = b2[(size_t)c * Oo + col];
        #pragma unroll
        for (int pp = 0; pp < 4; pp++) {
            int iA = 2 * (p0 + pp), iB = iA + 1;
            int tA = (iA < cnt) ? g_perm[start + iA] : -1;
            int tB = (iB < cnt) ? g_perm[start + iB] : -1;
            float lo, hi;
            UNPK2(lo, hi, acc2[pp]);
            if (tA >= 0) out[(size_t)tA * Oo + col] = lo + bb;
            if (tB >= 0) out[(size_t)tB * Oo + col] = hi + bb;
        }
    }
}

extern "C" void kernel_launch(void* const* d_in, const int* in_sizes, int n_in,
                              void* d_out, int out_size) {
    const float* x   = (const float*)d_in[0];
    const int*   cat = (const int*)  d_in[1];
    const float* W1  = (const float*)d_in[2];
    const float* b1  = (const float*)d_in[3];
    const float* W2  = (const float*)d_in[4];
    const float* b2  = (const float*)d_in[5];
    float* out = (float*)d_out;

    size_t smem = (size_t)(Dd * Hh + Hh * Oo + NPAIR * XSTRIDE) * sizeof(float); // 114688 B
    static bool attr_set = false;
    if (!attr_set) {
        cudaFuncSetAttribute(k_mlp, cudaFuncAttributeMaxDynamicSharedMemorySize, (int)smem);
        attr_set = true;
    }

    k_histscan<<<NB, BT>>>(cat);
    k_scatter<<<NB, BT>>>(cat);
    k_mlp<<<MAXW, 256, smem>>>(x, W1, b1, W2, b2, out);
}

// round 5
// speedup vs baseline: 1.1343x; 1.1343x over previous
#include <cuda_runtime.h>

#define Nn 8192
#define Cc 100
#define Dd 128
#define Hh 128
#define Oo 64
#define TPC 32                 // tokens per CTA chunk
#define NPAIR (TPC / 2)        // 16 token pairs
#define XSTRIDE 260            // words per pair-row (128 f32x2 + 4 pad -> bank-spread)
#define MAXW 356
#define NB 16
#define BT 512

// ---------------- packed f32x2 helpers ----------------
#define FMA2(d, a, b) asm("fma.rn.f32x2 %0, %1, %2, %0;" : "+l"(d) : "l"(a), "l"(b))
#define DUP2(d, s)    asm("mov.b64 %0, {%1, %1};" : "=l"(d) : "f"(s))
#define PK2(d, lo, hi) asm("mov.b64 %0, {%1, %2};" : "=l"(d) : "f"(lo), "f"(hi))
#define UNPK2(lo, hi, s) asm("mov.b64 {%0, %1}, %2;" : "=f"(lo), "=f"(hi) : "l"(s))

// ---------------- scratch (no allocations allowed) ----------------
__device__ int g_bhist[NB * Cc];
__device__ int g_perm[Nn];

// per-block histogram: SMEM atomics only
__global__ void k_hist(const int* __restrict__ cat) {
    __shared__ int h[Cc];
    int t = threadIdx.x, b = blockIdx.x;
    if (t < Cc) h[t] = 0;
    __syncthreads();
    atomicAdd(&h[cat[b * BT + t]], 1);
    __syncthreads();
    if (t < Cc) g_bhist[b * Cc + t] = h[t];
}

// scatter: each block computes its own per-category base via smem scan,
// then scatters with SMEM cursor atomics only.
__global__ void k_scatter(const int* __restrict__ cat) {
    __shared__ int s_scan[128];
    __shared__ int s_cur[Cc];
    int t = threadIdx.x, b = blockIdx.x;
    int p_mine = 0, pre = 0;
    if (t < 128) {
        int tot = 0;
        if (t < Cc) {
            #pragma unroll
            for (int bb = 0; bb < NB; bb++) {
                int v = g_bhist[bb * Cc + t];
                tot += v;
                if (bb < b) pre += v;
            }
        }
        p_mine = tot;
        s_scan[t] = tot;
    }
    __syncthreads();
    #pragma unroll
    for (int d = 1; d < 128; d <<= 1) {
        int v = 0;
        if (t < 128 && t >= d) v = s_scan[t - d];
        __syncthreads();
        if (t < 128) s_scan[t] += v;
        __syncthreads();
    }
    if (t < Cc) s_cur[t] = (s_scan[t] - p_mine) + pre;   // offEx[c] + prior-block counts
    __syncthreads();
    int id = b * BT + t;
    int pos = atomicAdd(&s_cur[cat[id]], 1);
    g_perm[pos] = id;
}

// ---------------- main fused MLP: one CTA = (category, 32-token chunk) ----------------
// Worklist computed in-CTA via packed scan (tot | nchunks<<16) of g_bhist.
// Layer 1: warp = 8 pairs x 32 cols; lane = 2 pairs x 4 cols.
// Layer 2: warp = 8 pairs x 16 cols; lane = 2 pairs x 2 cols.
// SMEM = W1 64KB + W2 32KB + xp 16.25KB -> 2 CTAs/SM. h overwrites xp in place.
__global__ void __launch_bounds__(256, 2)
k_mlp(const float* __restrict__ x,
      const float* __restrict__ W1, const float* __restrict__ b1,
      const float* __restrict__ W2, const float* __restrict__ b2,
      float* __restrict__ out) {
    __shared__ int s_scan[128];
    __shared__ int s_c, s_start, s_cnt;
    extern __shared__ float sm[];
    float* W1s = sm;                      // 16384 f (64KB)  [d][h]
    float* W2s = W1s + Dd * Hh;           // 8192 f  (32KB)  [k][o]
    float* xp  = W2s + Hh * Oo;           // 16*260 f : pair-major packed x / h

    int t = threadIdx.x;
    int w = blockIdx.x;

    // ---- in-CTA worklist: packed scan over categories ----
    int p_mine = 0;
    if (t < 128) {
        int tot = 0;
        if (t < Cc) {
            #pragma unroll
            for (int b = 0; b < NB; b++) tot += g_bhist[b * Cc + t];
        }
        p_mine = tot | (((tot + TPC - 1) / TPC) << 16);
        s_scan[t] = p_mine;
    }
    __syncthreads();
    #pragma unroll
    for (int d = 1; d < 128; d <<= 1) {
        int v = 0;
        if (t < 128 && t >= d) v = s_scan[t - d];
        __syncthreads();
        if (t < 128) s_scan[t] += v;
        __syncthreads();
    }
    if (t < Cc) {
        int excl = s_scan[t] - p_mine;
        int coffEx = excl >> 16;
        int nch = p_mine >> 16;
        if (w >= coffEx && w < coffEx + nch) {
            int j = w - coffEx;
            s_c = t;
            s_start = (excl & 0xFFFF) + j * TPC;
            int rem = (p_mine & 0xFFFF) - j * TPC;
            s_cnt = rem < TPC ? rem : TPC;
        }
    }
    __syncthreads();
    if (w >= (s_scan[127] >> 16)) return;
    int c = s_c, start = s_start, cnt = s_cnt;

    // ---- stage weights (coalesced float4) ----
    const float4* W1g = (const float4*)(W1 + (size_t)c * Dd * Hh);
    float4* W1s4 = (float4*)W1s;
    #pragma unroll 4
    for (int i = t; i < Dd * Hh / 4; i += 256) W1s4[i] = W1g[i];
    const float4* W2g = (const float4*)(W2 + (size_t)c * Hh * Oo);
    float4* W2s4 = (float4*)W2s;
    #pragma unroll 2
    for (int i = t; i < Hh * Oo / 4; i += 256) W2s4[i] = W2g[i];

    // ---- stage x transposed+pair-packed: xp[p][d] = (x_{2p}[d], x_{2p+1}[d]) ----
    #pragma unroll
    for (int i = t; i < NPAIR * 32; i += 256) {
        int p = i >> 5, q = i & 31;            // q indexes d-quads
        int iA = 2 * p, iB = 2 * p + 1;
        int tA = (iA < cnt) ? g_perm[start + iA] : -1;
        int tB = (iB < cnt) ? g_perm[start + iB] : -1;
        float4 a = (tA >= 0) ? ((const float4*)(x + (size_t)tA * Dd))[q]
                             : make_float4(0.f, 0.f, 0.f, 0.f);
        float4 bb = (tB >= 0) ? ((const float4*)(x + (size_t)tB * Dd))[q]
                              : make_float4(0.f, 0.f, 0.f, 0.f);
        float* dst = xp + (size_t)p * XSTRIDE + 8 * q;
        ((float4*)dst)[0] = make_float4(a.x, bb.x, a.y, bb.y);
        ((float4*)dst)[1] = make_float4(a.z, bb.z, a.w, bb.w);
    }
    __syncthreads();

    int warp = t >> 5, lane = t & 31;
    int pg = warp & 1;                     // pair group (8 pairs)
    int cg = warp >> 1;                    // col group
    int p0 = 8 * pg + 2 * (lane & 3);      // lane's 2 pairs
    int cbase = 32 * cg + 4 * (lane >> 2); // lane's 4 cols (layer 1)

    // ---- layer 1: acc[pair][col] = 8 packed accumulators ----
    unsigned long long acc[2][4];
    #pragma unroll
    for (int pp = 0; pp < 2; pp++)
        #pragma unroll
        for (int j = 0; j < 4; j++) acc[pp][j] = 0ULL;

    #pragma unroll 4
    for (int d = 0; d < Dd; d += 2) {
        ulonglong2 xv0 = *(const ulonglong2*)(xp + (size_t)(p0 + 0) * XSTRIDE + 2 * d);
        ulonglong2 xv1 = *(const ulonglong2*)(xp + (size_t)(p0 + 1) * XSTRIDE + 2 * d);
        float4 wa = *(const float4*)(W1s + (size_t)d * Hh + cbase);
        float4 wb = *(const float4*)(W1s + (size_t)(d + 1) * Hh + cbase);
        unsigned long long a0, a1, a2w, a3, b0, b1, b2w, b3;
        DUP2(a0, wa.x); DUP2(a1, wa.y); DUP2(a2w, wa.z); DUP2(a3, wa.w);
        DUP2(b0, wb.x); DUP2(b1, wb.y); DUP2(b2w, wb.z); DUP2(b3, wb.w);
        FMA2(acc[0][0], xv0.x, a0); FMA2(acc[0][1], xv0.x, a1);
        FMA2(acc[0][2], xv0.x, a2w); FMA2(acc[0][3], xv0.x, a3);
        FMA2(acc[1][0], xv1.x, a0); FMA2(acc[1][1], xv1.x, a1);
        FMA2(acc[1][2], xv1.x, a2w); FMA2(acc[1][3], xv1.x, a3);
        FMA2(acc[0][0], xv0.y, b0); FMA2(acc[0][1], xv0.y, b1);
        FMA2(acc[0][2], xv0.y, b2w); FMA2(acc[0][3], xv0.y, b3);
        FMA2(acc[1][0], xv1.y, b0); FMA2(acc[1][1], xv1.y, b1);
        FMA2(acc[1][2], xv1.y, b2w); FMA2(acc[1][3], xv1.y, b3);
    }

    __syncthreads();   // all warps done reading xp before h overwrites it

    // epilogue 1: bias + relu, store pair-packed h in place over xp
    {
        float4 bv = *(const float4*)(b1 + (size_t)c * Hh + cbase);
        float bj[4] = {bv.x, bv.y, bv.z, bv.w};
        #pragma unroll
        for (int pp = 0; pp < 2; pp++) {
            ulonglong2 v;
            float l0, h0, l1, h1, l2, h2, l3, h3;
            UNPK2(l0, h0, acc[pp][0]);
            UNPK2(l1, h1, acc[pp][1]);
            UNPK2(l2, h2, acc[pp][2]);
            UNPK2(l3, h3, acc[pp][3]);
            l0 = fmaxf(l0 + bj[0], 0.f); h0 = fmaxf(h0 + bj[0], 0.f);
            l1 = fmaxf(l1 + bj[1], 0.f); h1 = fmaxf(h1 + bj[1], 0.f);
            PK2(v.x, l0, h0); PK2(v.y, l1, h1);
            *(ulonglong2*)(xp + (size_t)(p0 + pp) * XSTRIDE + 2 * cbase) = v;
            l2 = fmaxf(l2 + bj[2], 0.f); h2 = fmaxf(h2 + bj[2], 0.f);
            l3 = fmaxf(l3 + bj[3], 0.f); h3 = fmaxf(h3 + bj[3], 0.f);
            PK2(v.x, l2, h2); PK2(v.y, l3, h3);
            *(ulonglong2*)(xp + (size_t)(p0 + pp) * XSTRIDE + 2 * cbase + 4) = v;
        }
    }

    __syncthreads();   // h complete before layer 2 reads

    // ---- layer 2: a2[pair][col] = 4 packed accumulators ----
    int cb2 = 16 * cg + 2 * (lane >> 2);   // lane's 2 cols (layer 2)
    unsigned long long acc2[2][2];
    acc2[0][0] = acc2[0][1] = acc2[1][0] = acc2[1][1] = 0ULL;

    #pragma unroll 4
    for (int k = 0; k < Hh; k += 2) {
        ulonglong2 h0 = *(const ulonglong2*)(xp + (size_t)(p0 + 0) * XSTRIDE + 2 * k);
        ulonglong2 h1 = *(const ulonglong2*)(xp + (size_t)(p0 + 1) * XSTRIDE + 2 * k);
        float2 wA = *(const float2*)(W2s + (size_t)k * Oo + cb2);
        float2 wB = *(const float2*)(W2s + (size_t)(k + 1) * Oo + cb2);
        unsigned long long wA0, wA1, wB0, wB1;
        DUP2(wA0, wA.x); DUP2(wA1, wA.y);
        DUP2(wB0, wB.x); DUP2(wB1, wB.y);
        FMA2(acc2[0][0], h0.x, wA0); FMA2(acc2[0][1], h0.x, wA1);
        FMA2(acc2[1][0], h1.x, wA0); FMA2(acc2[1][1], h1.x, wA1);
        FMA2(acc2[0][0], h0.y, wB0); FMA2(acc2[0][1], h0.y, wB1);
        FMA2(acc2[1][0], h1.y, wB0); FMA2(acc2[1][1], h1.y, wB1);
    }

    // epilogue 2: bias + store (unpack token pairs)
    {
        float2 b2v = *(const float2*)(b2 + (size_t)c * Oo + cb2);
        #pragma unroll
        for (int pp = 0; pp < 2; pp++) {
            int iA = 2 * (p0 + pp), iB = iA + 1;
            int tA = (iA < cnt) ? g_perm[start + iA] : -1;
            int tB = (iB < cnt) ? g_perm[start + iB] : -1;
            float l0, h0, l1, h1;
            UNPK2(l0, h0, acc2[pp][0]);
            UNPK2(l1, h1, acc2[pp][1]);
            if (tA >= 0) {
                float2 o; o.x = l0 + b2v.x; o.y = l1 + b2v.y;
                *(float2*)(out + (size_t)tA * Oo + cb2) = o;
            }
            if (tB >= 0) {
                float2 o; o.x = h0 + b2v.x; o.y = h1 + b2v.y;
                *(float2*)(out + (size_t)tB * Oo + cb2) = o;
            }
        }
    }
}

extern "C" void kernel_launch(void* const* d_in, const int* in_sizes, int n_in,
                              void* d_out, int out_size) {
    const float* x   = (const float*)d_in[0];
    const int*   cat = (const int*)  d_in[1];
    const float* W1  = (const float*)d_in[2];
    const float* b1  = (const float*)d_in[3];
    const float* W2  = (const float*)d_in[4];
    const float* b2  = (const float*)d_in[5];
    float* out = (float*)d_out;

    size_t smem = (size_t)(Dd * Hh + Hh * Oo + NPAIR * XSTRIDE) * sizeof(float); // 114944 B
    static bool attr_set = false;
    if (!attr_set) {
        cudaFuncSetAttribute(k_mlp, cudaFuncAttributeMaxDynamicSharedMemorySize, (int)smem);
        attr_set = true;
    }

    k_hist<<<NB, BT>>>(cat);
    k_scatter<<<NB, BT>>>(cat);
    k_mlp<<<MAXW, 256, smem>>>(x, W1, b1, W2, b2, out);
}